// round 1
// baseline (speedup 1.0000x reference)
#include <cuda_runtime.h>
#include <math.h>

// Problem constants (fixed shapes)
#define HH   256
#define NN   64
#define LL   2048
#define FF   1025   // L/2 + 1
#define MM   1024   // L/2

// Intermediate frequency-domain kernel k_f: (H, F) complex
__device__ float2 g_kf[HH * FF];

// ---------------------------------------------------------------------------
// Kernel 1: Cauchy + Woodbury -> k_f
// One block per h. 128 threads; each thread owns 8 frequencies f = tid + 128*k.
// Shared per-n data (10 floats) is loaded once per n and reused across 8 f's.
// ---------------------------------------------------------------------------
__global__ __launch_bounds__(128)
void cauchy_kernel(const float* __restrict__ Cin, const float* __restrict__ Bin,
                   const float* __restrict__ Pin, const float* __restrict__ Win,
                   const float* __restrict__ logdt) {
    const int h   = blockIdx.x;
    const int tid = threadIdx.x;

    __shared__ float4 sv0[NN];   // v00r, v00i, v01r, v01i
    __shared__ float4 sv1[NN];   // v10r, v10i, v11r (real), -w_dt_r
    __shared__ float2 sv2[NN];   // w_dt_i, (w_dt_r)^2

    const float dt = expf(logdt[h]);

    if (tid < NN) {
        const int base = h * (NN * 2) + tid * 2;
        float cr = Cin[base], ci = Cin[base + 1];
        float br = Bin[base], bi = Bin[base + 1];
        float pr = Pin[base], pi = Pin[base + 1];
        float wr = Win[base], wi = Win[base + 1];
        float wdr = wr * dt, wdi = wi * dt;
        float4 v0, v1; float2 v2;
        v0.x = br * cr - bi * ci;     // v00 = B*C
        v0.y = br * ci + bi * cr;
        v0.z = br * pr + bi * pi;     // v01 = B*conj(P)
        v0.w = bi * pr - br * pi;
        v1.x = pr * cr - pi * ci;     // v10 = P*C
        v1.y = pr * ci + pi * cr;
        v1.z = pr * pr + pi * pi;     // v11 = |P|^2 (purely real)
        v1.w = -wdr;                  // denominator real part (z_r == 0)
        v2.x = wdi;
        v2.y = wdr * wdr;
        sv0[tid] = v0; sv1[tid] = v1; sv2[tid] = v2;
    }
    __syncthreads();

    // z_f = 2*i*tan(pi*f/L); gain 2/(1+omega) = 1 + i*tan(pi*f/L)
    float zi[8];
#pragma unroll
    for (int k = 0; k < 8; k++) {
        int f = tid + 128 * k;          // 0..1023
        float s, c;
        sincospif((float)f * (1.0f / LL), &s, &c);
        zi[k] = 2.0f * __fdividef(s, c);
    }

    float a00r[8], a00i[8], a01r[8], a01i[8], a10r[8], a10i[8], a11r[8], a11i[8];
#pragma unroll
    for (int k = 0; k < 8; k++) {
        a00r[k] = a00i[k] = a01r[k] = a01i[k] = 0.f;
        a10r[k] = a10i[k] = a11r[k] = a11i[k] = 0.f;
    }

    for (int n = 0; n < NN; n++) {
        const float4 p0 = sv0[n];
        const float4 p1 = sv1[n];
        const float2 p2 = sv2[n];
#pragma unroll
        for (int k = 0; k < 8; k++) {
            float di  = zi[k] - p2.x;
            float den = fmaf(di, di, p2.y);
            float inv;
            asm("rcp.approx.f32 %0, %1;" : "=f"(inv) : "f"(den));
            float tr = p1.w * inv;      // Re 1/(z-w) = -wdr/|d|^2
            float ti = -di * inv;       // Im 1/(z-w)
            a00r[k] += p0.x * tr - p0.y * ti;
            a00i[k] += p0.x * ti + p0.y * tr;
            a01r[k] += p0.z * tr - p0.w * ti;
            a01i[k] += p0.z * ti + p0.w * tr;
            a10r[k] += p1.x * tr - p1.y * ti;
            a10i[k] += p1.x * ti + p1.y * tr;
            a11r[k] += p1.z * tr;       // v11 imag == 0
            a11i[k] += p1.z * ti;
        }
    }

#pragma unroll
    for (int k = 0; k < 8; k++) {
        int f = tid + 128 * k;
        float r00r = dt * a00r[k], r00i = dt * a00i[k];
        float r01r = dt * a01r[k], r01i = dt * a01i[k];
        float r10r = dt * a10r[k], r10i = dt * a10i[k];
        float r11r = dt * a11r[k], r11i = dt * a11i[k];
        // q = r01*r10 / (1 + r11)
        float numr = r01r * r10r - r01i * r10i;
        float numi = r01r * r10i + r01i * r10r;
        float denr = 1.0f + r11r;
        float deni = r11i;
        float dd   = denr * denr + deni * deni;
        float dinv;
        asm("rcp.approx.f32 %0, %1;" : "=f"(dinv) : "f"(dd));
        float qr = (numr * denr + numi * deni) * dinv;
        float qi = (numi * denr - numr * deni) * dinv;
        float xr = r00r - qr;
        float xi = r00i - qi;
        // * gain (1 + i*gi), gi = tan(pi f / L) = zi/2
        float gi = 0.5f * zi[k];
        g_kf[h * FF + f] = make_float2(xr - xi * gi, xr * gi + xi);
    }

    // Nyquist bin f = L/2: removable singularity; limit = 0.5*dt*sum_n v00
    if (tid == 0) {
        float sr = 0.f, si = 0.f;
        for (int n = 0; n < NN; n++) { sr += sv0[n].x; si += sv0[n].y; }
        (void)si;  // imag part is discarded by irfft convention
        g_kf[h * FF + MM] = make_float2(0.5f * dt * sr, 0.f);
    }
}

// ---------------------------------------------------------------------------
// Kernel 2: length-2048 irfft per h via 1024-point complex inverse FFT.
// Z[k] = E[k] + i*O[k],
//   E[k] = (X[k] + conj(X[M-k]))/2
//   O[k] = e^{+2*pi*i*k/L} * (X[k] - conj(X[M-k]))/2
// z = iDFT_M(Z) (1/M folded into build, total scale 1/2048);
// x[2n] = Re z[n], x[2n+1] = Im z[n].
// Radix-2 DIF (natural in, bit-reversed out), conj twiddles (inverse).
// ---------------------------------------------------------------------------
__global__ __launch_bounds__(256)
void ifft_kernel(float* __restrict__ out) {
    const int h   = blockIdx.x;
    const int tid = threadIdx.x;
    __shared__ float Zr[MM];
    __shared__ float Zi[MM];

    const float2* kf = g_kf + h * FF;
    const float sc = 1.0f / 2048.0f;

#pragma unroll
    for (int j = 0; j < 4; j++) {
        int k = tid + 256 * j;
        float2 Xk = kf[k];
        float2 Xm = kf[MM - k];
        if (k == 0) { Xk.y = 0.f; Xm.y = 0.f; }  // drop imag of DC & Nyquist
        float er  = (Xk.x + Xm.x) * sc;
        float ei  = (Xk.y - Xm.y) * sc;
        float pr  = (Xk.x - Xm.x) * sc;
        float pi_ = (Xk.y + Xm.y) * sc;
        float s, c;
        sincospif((float)k * (1.0f / MM), &s, &c);  // e^{+i*pi*k/1024}
        float Or = pr * c - pi_ * s;
        float Oi = pr * s + pi_ * c;
        Zr[k] = er - Oi;            // Z = E + i*O
        Zi[k] = ei + Or;
    }
    __syncthreads();

    // inverse DIF stages
    for (int half = MM / 2; half >= 1; half >>= 1) {
        const int tmul = (MM / 2) / half;
#pragma unroll
        for (int b2 = 0; b2 < 2; b2++) {
            int b  = tid + 256 * b2;              // butterfly 0..511
            int j  = b & (half - 1);
            int i0 = ((b - j) << 1) + j;
            int i1 = i0 + half;
            float ar = Zr[i0], ai = Zi[i0];
            float br = Zr[i1], bi = Zi[i1];
            float sr = ar + br, si = ai + bi;
            float dr = ar - br, di = ai - bi;
            float s, c;
            sincospif((float)(j * tmul) * (1.0f / 512.0f), &s, &c);  // e^{+2pi i t/1024}
            Zr[i0] = sr; Zi[i0] = si;
            Zr[i1] = dr * c - di * s;
            Zi[i1] = dr * s + di * c;
        }
        __syncthreads();
    }

    // de-interleave + bit-reversal permutation, vectorized float2 stores
    float2* out2 = reinterpret_cast<float2*>(out + h * LL);
#pragma unroll
    for (int j = 0; j < 4; j++) {
        int p = tid + 256 * j;
        int n = __brev((unsigned)p) >> 22;        // 10-bit reverse
        out2[n] = make_float2(Zr[p], Zi[p]);
    }
}

extern "C" void kernel_launch(void* const* d_in, const int* in_sizes, int n_in,
                              void* d_out, int out_size) {
    (void)in_sizes; (void)n_in; (void)out_size;
    const float* C  = (const float*)d_in[0];
    const float* B  = (const float*)d_in[1];
    const float* P  = (const float*)d_in[2];
    const float* W  = (const float*)d_in[3];
    const float* ld = (const float*)d_in[4];

    cauchy_kernel<<<HH, 128>>>(C, B, P, W, ld);
    ifft_kernel<<<HH, 256>>>((float*)d_out);
}

// round 3
// speedup vs baseline: 1.4215x; 1.4215x over previous
#include <cuda_runtime.h>
#include <math.h>
#include <stdint.h>

#define HH   256
#define NN   64
#define LL   2048
#define FF   1025
#define MM   1024
#define TPB  256

// ---- f32x2 packed helpers (Blackwell PTX ISA 8.6+) ----
__device__ __forceinline__ uint64_t pk2(float lo, float hi) {
    uint64_t r; asm("mov.b64 %0,{%1,%2};" : "=l"(r) : "f"(lo), "f"(hi)); return r;
}
__device__ __forceinline__ void up2(uint64_t v, float& lo, float& hi) {
    asm("mov.b64 {%0,%1},%2;" : "=f"(lo), "=f"(hi) : "l"(v));
}
__device__ __forceinline__ uint64_t sub2(uint64_t a, uint64_t b) {
    uint64_t d; asm("sub.rn.f32x2 %0,%1,%2;" : "=l"(d) : "l"(a), "l"(b)); return d;
}
__device__ __forceinline__ uint64_t mul2(uint64_t a, uint64_t b) {
    uint64_t d; asm("mul.rn.f32x2 %0,%1,%2;" : "=l"(d) : "l"(a), "l"(b)); return d;
}
__device__ __forceinline__ uint64_t fma2(uint64_t a, uint64_t b, uint64_t c) {
    uint64_t d; asm("fma.rn.f32x2 %0,%1,%2,%3;" : "=l"(d) : "l"(a), "l"(b), "l"(c)); return d;
}
__device__ __forceinline__ uint64_t rcp2(uint64_t v) {
    float lo, hi; up2(v, lo, hi);
    float a, b;
    asm("rcp.approx.f32 %0,%1;" : "=f"(a) : "f"(lo));
    asm("rcp.approx.f32 %0,%1;" : "=f"(b) : "f"(hi));
    return pk2(a, b);
}

// Woodbury + bilinear gain epilogue for one frequency -> X in smem
__device__ __forceinline__ void woodbury(float A00r, float A00i, float A01r, float A01i,
                                         float A10r, float A10i, float A11r, float A11i,
                                         float dt, float gi, int f,
                                         float* __restrict__ Xr, float* __restrict__ Xi) {
    float r00r = dt * A00r, r00i = dt * A00i;
    float r01r = dt * A01r, r01i = dt * A01i;
    float r10r = dt * A10r, r10i = dt * A10i;
    float r11r = dt * A11r, r11i = dt * A11i;
    float numr = r01r * r10r - r01i * r10i;
    float numi = r01r * r10i + r01i * r10r;
    float denr = 1.0f + r11r;
    float deni = r11i;
    float dd   = denr * denr + deni * deni;
    float dinv; asm("rcp.approx.f32 %0,%1;" : "=f"(dinv) : "f"(dd));
    float qr = (numr * denr + numi * deni) * dinv;
    float qi = (numi * denr - numr * deni) * dinv;
    float xr = r00r - qr;
    float xi = r00i - qi;
    Xr[f] = xr - xi * gi;      // * (1 + i*gi), gi = tan(pi f / L)
    Xi[f] = xr * gi + xi;
}

// ---------------------------------------------------------------------------
// Fused kernel: one block per h.
// Phase 1 (Cauchy + Woodbury, f32x2-packed): 256 threads, 4 freqs/thread
//   packed as 2 f32x2 lanes; per-n constants (lane-doubled) in smem.
// Phase 2 (irfft L=2048 via 1024-pt complex inverse FFT), all in smem.
// ---------------------------------------------------------------------------
__global__ __launch_bounds__(TPB)
void fused_kernel(const float* __restrict__ Cin, const float* __restrict__ Bin,
                  const float* __restrict__ Pin, const float* __restrict__ Win,
                  const float* __restrict__ logdt, float* __restrict__ out) {
    __shared__ uint64_t sc[NN * 10];       // lane-doubled per-n constants
    __shared__ float Xr[FF + 3], Xi[FF + 3];
    __shared__ float Zr[MM], Zi[MM];

    const int h   = blockIdx.x;
    const int tid = threadIdx.x;
    const float dt = expf(logdt[h]);

    if (tid < NN) {
        const int base = h * (NN * 2) + tid * 2;
        float cr = Cin[base], ci = Cin[base + 1];
        float br = Bin[base], bi = Bin[base + 1];
        float pr = Pin[base], pi = Pin[base + 1];
        float wr = Win[base], wi = Win[base + 1];
        float wdr = wr * dt, wdi = wi * dt;
        uint64_t* p = &sc[tid * 10];
        p[0] = pk2(wdi, wdi);
        p[1] = pk2(wdr * wdr, wdr * wdr);
        p[2] = pk2(-wdr, -wdr);
        float v00r = br * cr - bi * ci, v00i = br * ci + bi * cr;   // B*C
        float v01r = br * pr + bi * pi, v01i = bi * pr - br * pi;   // B*conj(P)
        float v10r = pr * cr - pi * ci, v10i = pr * ci + pi * cr;   // P*C
        float v11r = pr * pr + pi * pi;                             // |P|^2 (real)
        p[3] = pk2(v00r, v00r); p[4] = pk2(v00i, v00i);
        p[5] = pk2(v01r, v01r); p[6] = pk2(v01i, v01i);
        p[7] = pk2(v10r, v10r); p[8] = pk2(v10i, v10i);
        p[9] = pk2(v11r, v11r);
    }
    __syncthreads();

    // z_f = 2*i*tan(pi f / L); pair j covers freqs (tid+512j, tid+256+512j)
    uint64_t zi[2];
#pragma unroll
    for (int j = 0; j < 2; j++) {
        int f0 = tid + 512 * j;
        int f1 = f0 + 256;
        float s0, c0, s1, c1;
        sincospif((float)f0 * (1.0f / LL), &s0, &c0);
        sincospif((float)f1 * (1.0f / LL), &s1, &c1);
        zi[j] = pk2(2.0f * __fdividef(s0, c0), 2.0f * __fdividef(s1, c1));
    }

    uint64_t a00r[2] = {0, 0}, a00i[2] = {0, 0};
    uint64_t a01r[2] = {0, 0}, a01i[2] = {0, 0};
    uint64_t a10r[2] = {0, 0}, a10i[2] = {0, 0};
    uint64_t a11r[2] = {0, 0}, a11i[2] = {0, 0};

#pragma unroll 2
    for (int n = 0; n < NN; n++) {
        const uint64_t* p = &sc[n * 10];
        uint64_t wdi  = p[0], wdr2 = p[1], nwdr = p[2];
        uint64_t v00r = p[3], v00i = p[4];
        uint64_t v01r = p[5], v01i = p[6];
        uint64_t v10r = p[7], v10i = p[8];
        uint64_t v11r = p[9];
#pragma unroll
        for (int j = 0; j < 2; j++) {
            // denom = z - w_dt = -wdr + i*(zi - wdi)
            uint64_t D   = sub2(zi[j], wdi);     //  Im(denom)
            uint64_t nD  = sub2(wdi, zi[j]);     // -Im(denom)
            uint64_t den = fma2(D, D, wdr2);     // |denom|^2
            uint64_t inv = rcp2(den);
            uint64_t tr  = mul2(nwdr, inv);      //  Re 1/denom
            uint64_t ti  = mul2(nD, inv);        //  Im 1/denom
            uint64_t mti = mul2(D, inv);         // -Im 1/denom
            a00r[j] = fma2(v00r, tr, a00r[j]); a00r[j] = fma2(v00i, mti, a00r[j]);
            a00i[j] = fma2(v00r, ti, a00i[j]); a00i[j] = fma2(v00i, tr,  a00i[j]);
            a01r[j] = fma2(v01r, tr, a01r[j]); a01r[j] = fma2(v01i, mti, a01r[j]);
            a01i[j] = fma2(v01r, ti, a01i[j]); a01i[j] = fma2(v01i, tr,  a01i[j]);
            a10r[j] = fma2(v10r, tr, a10r[j]); a10r[j] = fma2(v10i, mti, a10r[j]);
            a10i[j] = fma2(v10r, ti, a10i[j]); a10i[j] = fma2(v10i, tr,  a10i[j]);
            a11r[j] = fma2(v11r, tr, a11r[j]);
            a11i[j] = fma2(v11r, ti, a11i[j]);
        }
    }

    // Epilogue: unpack, Woodbury, gain, write X to smem
#pragma unroll
    for (int j = 0; j < 2; j++) {
        float b00r, c00r, b00i, c00i, b01r, c01r, b01i, c01i;
        float b10r, c10r, b10i, c10i, b11r, c11r, b11i, c11i;
        float zlo, zhi;
        up2(a00r[j], b00r, c00r); up2(a00i[j], b00i, c00i);
        up2(a01r[j], b01r, c01r); up2(a01i[j], b01i, c01i);
        up2(a10r[j], b10r, c10r); up2(a10i[j], b10i, c10i);
        up2(a11r[j], b11r, c11r); up2(a11i[j], b11i, c11i);
        up2(zi[j], zlo, zhi);
        int f0 = tid + 512 * j;
        woodbury(b00r, b00i, b01r, b01i, b10r, b10i, b11r, b11i,
                 dt, 0.5f * zlo, f0, Xr, Xi);
        woodbury(c00r, c00i, c01r, c01i, c10r, c10i, c11r, c11i,
                 dt, 0.5f * zhi, f0 + 256, Xr, Xi);
    }

    // Nyquist bin f = L/2 (removable singularity): limit = 0.5*dt*sum_n v00
    if (tid == 0) {
        float sr = 0.f;
        for (int n = 0; n < NN; n++) {
            float lo, hi; up2(sc[n * 10 + 3], lo, hi); (void)hi;
            sr += lo;
        }
        Xr[MM] = 0.5f * dt * sr;
        Xi[MM] = 0.f;
    }
    __syncthreads();

    // ---- Phase 2: irfft via 1024-pt complex inverse FFT ----
    const float scl = 1.0f / 2048.0f;
#pragma unroll
    for (int j = 0; j < 4; j++) {
        int k = tid + 256 * j;
        float Xkx = Xr[k],      Xky = Xi[k];
        float Xmx = Xr[MM - k], Xmy = Xi[MM - k];
        if (k == 0) { Xky = 0.f; Xmy = 0.f; }   // drop imag of DC & Nyquist
        float er  = (Xkx + Xmx) * scl;
        float ei  = (Xky - Xmy) * scl;
        float pr  = (Xkx - Xmx) * scl;
        float pi_ = (Xky + Xmy) * scl;
        float s, c;
        sincospif((float)k * (1.0f / MM), &s, &c);  // e^{+i*pi*k/1024}
        float Or = pr * c - pi_ * s;
        float Oi = pr * s + pi_ * c;
        Zr[k] = er - Oi;            // Z = E + i*O
        Zi[k] = ei + Or;
    }
    __syncthreads();

    for (int half = MM / 2; half >= 1; half >>= 1) {
        const int tmul = (MM / 2) / half;
#pragma unroll
        for (int b2 = 0; b2 < 2; b2++) {
            int b  = tid + 256 * b2;
            int jj = b & (half - 1);
            int i0 = ((b - jj) << 1) + jj;
            int i1 = i0 + half;
            float ar = Zr[i0], ai = Zi[i0];
            float br = Zr[i1], bi = Zi[i1];
            float sr = ar + br, si = ai + bi;
            float dr = ar - br, di = ai - bi;
            float s, c;
            sincospif((float)(jj * tmul) * (1.0f / 512.0f), &s, &c);  // e^{+2pi i t/1024}
            Zr[i0] = sr; Zi[i0] = si;
            Zr[i1] = dr * c - di * s;
            Zi[i1] = dr * s + di * c;
        }
        __syncthreads();
    }

    float2* out2 = reinterpret_cast<float2*>(out + h * LL);
#pragma unroll
    for (int j = 0; j < 4; j++) {
        int p = tid + 256 * j;
        int n = __brev((unsigned)p) >> 22;   // 10-bit reverse
        out2[n] = make_float2(Zr[p], Zi[p]);
    }
}

extern "C" void kernel_launch(void* const* d_in, const int* in_sizes, int n_in,
                              void* d_out, int out_size) {
    (void)in_sizes; (void)n_in; (void)out_size;
    const float* C  = (const float*)d_in[0];
    const float* B  = (const float*)d_in[1];
    const float* P  = (const float*)d_in[2];
    const float* W  = (const float*)d_in[3];
    const float* ld = (const float*)d_in[4];
    fused_kernel<<<HH, TPB>>>(C, B, P, W, ld, (float*)d_out);
}

// round 4
// speedup vs baseline: 1.5129x; 1.0643x over previous
#include <cuda_runtime.h>
#include <math.h>
#include <stdint.h>

#define HH   256
#define NN   64
#define LL   2048
#define FF   1025
#define MM   1024
#define TPB  256

// ---- f32x2 packed helpers (Blackwell) ----
__device__ __forceinline__ uint64_t pk2(float lo, float hi) {
    uint64_t r; asm("mov.b64 %0,{%1,%2};" : "=l"(r) : "f"(lo), "f"(hi)); return r;
}
__device__ __forceinline__ void up2(uint64_t v, float& lo, float& hi) {
    asm("mov.b64 {%0,%1},%2;" : "=f"(lo), "=f"(hi) : "l"(v));
}
__device__ __forceinline__ uint64_t sub2(uint64_t a, uint64_t b) {
    uint64_t d; asm("sub.rn.f32x2 %0,%1,%2;" : "=l"(d) : "l"(a), "l"(b)); return d;
}
__device__ __forceinline__ uint64_t mul2(uint64_t a, uint64_t b) {
    uint64_t d; asm("mul.rn.f32x2 %0,%1,%2;" : "=l"(d) : "l"(a), "l"(b)); return d;
}
__device__ __forceinline__ uint64_t fma2(uint64_t a, uint64_t b, uint64_t c) {
    uint64_t d; asm("fma.rn.f32x2 %0,%1,%2,%3;" : "=l"(d) : "l"(a), "l"(b), "l"(c)); return d;
}
__device__ __forceinline__ uint64_t rcp2(uint64_t v) {
    float lo, hi; up2(v, lo, hi);
    float a, b;
    asm("rcp.approx.f32 %0,%1;" : "=f"(a) : "f"(lo));
    asm("rcp.approx.f32 %0,%1;" : "=f"(b) : "f"(hi));
    return pk2(a, b);
}
__device__ __forceinline__ float lanesum(uint64_t v) {
    float lo, hi; up2(v, lo, hi); return lo + hi;
}

// Woodbury + bilinear gain epilogue for one frequency -> X in smem
__device__ __forceinline__ void woodbury(float A00r, float A00i, float A01r, float A01i,
                                         float A10r, float A10i, float A11r, float A11i,
                                         float dt, float gi, int f,
                                         float* __restrict__ Xr, float* __restrict__ Xi) {
    float r00r = dt * A00r, r00i = dt * A00i;
    float r01r = dt * A01r, r01i = dt * A01i;
    float r10r = dt * A10r, r10i = dt * A10i;
    float r11r = dt * A11r, r11i = dt * A11i;
    float numr = r01r * r10r - r01i * r10i;
    float numi = r01r * r10i + r01i * r10r;
    float denr = 1.0f + r11r;
    float deni = r11i;
    float dd   = denr * denr + deni * deni;
    float dinv; asm("rcp.approx.f32 %0,%1;" : "=f"(dinv) : "f"(dd));
    float qr = (numr * denr + numi * deni) * dinv;
    float qi = (numi * denr - numr * deni) * dinv;
    float xr = r00r - qr;
    float xi = r00i - qi;
    Xr[f] = xr - xi * gi;      // * (1 + i*gi), gi = tan(pi f / L)
    Xi[f] = xr * gi + xi;
}

// ---------------------------------------------------------------------------
// Fused kernel, one block per h.
// Phase 1: Cauchy + Woodbury. f32x2 lanes = (n, n+1) pair; each thread owns
//   4 frequencies {tid, tid+256, tid+512, tid+768}. Per-n constants are
//   scalar in smem; one LDS.64 fetches an n-pair, reused across 4 freqs.
// Phase 2: irfft(L=2048) via 1024-pt complex inverse FFT in smem.
// ---------------------------------------------------------------------------
__global__ __launch_bounds__(TPB)
void fused_kernel(const float* __restrict__ Cin, const float* __restrict__ Bin,
                  const float* __restrict__ Pin, const float* __restrict__ Win,
                  const float* __restrict__ logdt, float* __restrict__ out) {
    // [const][n]: 0 wdi, 1 wdr2, 2 -wdr, 3 v00r, 4 v00i, 5 v01r, 6 v01i,
    //             7 v10r, 8 v10i, 9 v11r
    __shared__ __align__(16) float scn[10][NN];
    __shared__ float Xr[FF + 3], Xi[FF + 3];
    __shared__ float Zr[MM], Zi[MM];

    const int h   = blockIdx.x;
    const int tid = threadIdx.x;
    const float dt = expf(logdt[h]);

    if (tid < NN) {
        const int base = h * (NN * 2) + tid * 2;
        float cr = Cin[base], ci = Cin[base + 1];
        float br = Bin[base], bi = Bin[base + 1];
        float pr = Pin[base], pi = Pin[base + 1];
        float wr = Win[base], wi = Win[base + 1];
        float wdr = wr * dt, wdi = wi * dt;
        scn[0][tid] = wdi;
        scn[1][tid] = wdr * wdr;
        scn[2][tid] = -wdr;
        scn[3][tid] = br * cr - bi * ci;   // v00r = Re(B*C)
        scn[4][tid] = br * ci + bi * cr;   // v00i
        scn[5][tid] = br * pr + bi * pi;   // v01r = Re(B*conj(P))
        scn[6][tid] = bi * pr - br * pi;   // v01i
        scn[7][tid] = pr * cr - pi * ci;   // v10r = Re(P*C)
        scn[8][tid] = pr * ci + pi * cr;   // v10i
        scn[9][tid] = pr * pr + pi * pi;   // v11r = |P|^2 (real)
    }
    __syncthreads();

    // z_f = 2*i*tan(pi f / L); this thread's 4 freqs, each duplicated into lanes
    float zis[4];
    uint64_t zi[4];
#pragma unroll
    for (int j = 0; j < 4; j++) {
        int f = tid + 256 * j;
        float s, c;
        sincospif((float)f * (1.0f / LL), &s, &c);
        zis[j] = 2.0f * __fdividef(s, c);
        zi[j] = pk2(zis[j], zis[j]);
    }

    uint64_t a00r[4], a00i[4], a01r[4], a01i[4];
    uint64_t a10r[4], a10i[4], a11r[4], a11i[4];
#pragma unroll
    for (int j = 0; j < 4; j++) {
        a00r[j] = a00i[j] = a01r[j] = a01i[j] = 0;
        a10r[j] = a10i[j] = a11r[j] = a11i[j] = 0;
    }

    const uint64_t* s0 = (const uint64_t*)&scn[0][0];
    const uint64_t* s1 = (const uint64_t*)&scn[1][0];
    const uint64_t* s2 = (const uint64_t*)&scn[2][0];
    const uint64_t* s3 = (const uint64_t*)&scn[3][0];
    const uint64_t* s4 = (const uint64_t*)&scn[4][0];
    const uint64_t* s5 = (const uint64_t*)&scn[5][0];
    const uint64_t* s6 = (const uint64_t*)&scn[6][0];
    const uint64_t* s7 = (const uint64_t*)&scn[7][0];
    const uint64_t* s8 = (const uint64_t*)&scn[8][0];
    const uint64_t* s9 = (const uint64_t*)&scn[9][0];

#pragma unroll 2
    for (int m = 0; m < NN / 2; m++) {       // n-pair index
        uint64_t wdi  = s0[m], wdr2 = s1[m], nwdr = s2[m];
        uint64_t v00r = s3[m], v00i = s4[m];
        uint64_t v01r = s5[m], v01i = s6[m];
        uint64_t v10r = s7[m], v10i = s8[m];
        uint64_t v11r = s9[m];
#pragma unroll
        for (int j = 0; j < 4; j++) {
            // denom = -wdr + i*(zi - wdi); 1/denom = (-wdr - i*D) * inv
            uint64_t D   = sub2(zi[j], wdi);
            uint64_t den = fma2(D, D, wdr2);
            uint64_t inv = rcp2(den);
            uint64_t tr  = mul2(nwdr, inv);                  //  Re 1/denom
            uint64_t mti = mul2(D, inv);                     // -Im 1/denom
            uint64_t ti  = mti ^ 0x8000000080000000ULL;      //  Im (sign flip, ALU pipe)
            a00r[j] = fma2(v00r, tr, a00r[j]); a00r[j] = fma2(v00i, mti, a00r[j]);
            a00i[j] = fma2(v00r, ti, a00i[j]); a00i[j] = fma2(v00i, tr,  a00i[j]);
            a01r[j] = fma2(v01r, tr, a01r[j]); a01r[j] = fma2(v01i, mti, a01r[j]);
            a01i[j] = fma2(v01r, ti, a01i[j]); a01i[j] = fma2(v01i, tr,  a01i[j]);
            a10r[j] = fma2(v10r, tr, a10r[j]); a10r[j] = fma2(v10i, mti, a10r[j]);
            a10i[j] = fma2(v10r, ti, a10i[j]); a10i[j] = fma2(v10i, tr,  a10i[j]);
            a11r[j] = fma2(v11r, tr, a11r[j]);
            a11i[j] = fma2(v11r, ti, a11i[j]);
        }
    }

    // Epilogue: lane-sum (over n halves), Woodbury, gain, write X to smem
#pragma unroll
    for (int j = 0; j < 4; j++) {
        int f = tid + 256 * j;
        woodbury(lanesum(a00r[j]), lanesum(a00i[j]),
                 lanesum(a01r[j]), lanesum(a01i[j]),
                 lanesum(a10r[j]), lanesum(a10i[j]),
                 lanesum(a11r[j]), lanesum(a11i[j]),
                 dt, 0.5f * zis[j], f, Xr, Xi);
    }

    // Nyquist bin f = L/2 (removable singularity): limit = 0.5*dt*sum_n v00r
    if (tid == 0) {
        float sr = 0.f;
        for (int n = 0; n < NN; n++) sr += scn[3][n];
        Xr[MM] = 0.5f * dt * sr;
        Xi[MM] = 0.f;
    }
    __syncthreads();

    // ---- Phase 2: irfft via 1024-pt complex inverse FFT ----
    const float scl = 1.0f / 2048.0f;
#pragma unroll
    for (int j = 0; j < 4; j++) {
        int k = tid + 256 * j;
        float Xkx = Xr[k],      Xky = Xi[k];
        float Xmx = Xr[MM - k], Xmy = Xi[MM - k];
        if (k == 0) { Xky = 0.f; Xmy = 0.f; }   // drop imag of DC & Nyquist
        float er  = (Xkx + Xmx) * scl;
        float ei  = (Xky - Xmy) * scl;
        float pr  = (Xkx - Xmx) * scl;
        float pi_ = (Xky + Xmy) * scl;
        float s, c;
        sincospif((float)k * (1.0f / MM), &s, &c);  // e^{+i*pi*k/1024}
        float Or = pr * c - pi_ * s;
        float Oi = pr * s + pi_ * c;
        Zr[k] = er - Oi;            // Z = E + i*O
        Zi[k] = ei + Or;
    }
    __syncthreads();

    for (int half = MM / 2; half >= 1; half >>= 1) {
        const int tmul = (MM / 2) / half;
#pragma unroll
        for (int b2 = 0; b2 < 2; b2++) {
            int b  = tid + 256 * b2;
            int jj = b & (half - 1);
            int i0 = ((b - jj) << 1) + jj;
            int i1 = i0 + half;
            float ar = Zr[i0], ai = Zi[i0];
            float br = Zr[i1], bi = Zi[i1];
            float sr = ar + br, si = ai + bi;
            float dr = ar - br, di = ai - bi;
            float s, c;
            sincospif((float)(jj * tmul) * (1.0f / 512.0f), &s, &c);  // e^{+2pi i t/1024}
            Zr[i0] = sr; Zi[i0] = si;
            Zr[i1] = dr * c - di * s;
            Zi[i1] = dr * s + di * c;
        }
        __syncthreads();
    }

    float2* out2 = reinterpret_cast<float2*>(out + h * LL);
#pragma unroll
    for (int j = 0; j < 4; j++) {
        int p = tid + 256 * j;
        int n = __brev((unsigned)p) >> 22;   // 10-bit reverse
        out2[n] = make_float2(Zr[p], Zi[p]);
    }
}

extern "C" void kernel_launch(void* const* d_in, const int* in_sizes, int n_in,
                              void* d_out, int out_size) {
    (void)in_sizes; (void)n_in; (void)out_size;
    const float* C  = (const float*)d_in[0];
    const float* B  = (const float*)d_in[1];
    const float* P  = (const float*)d_in[2];
    const float* W  = (const float*)d_in[3];
    const float* ld = (const float*)d_in[4];
    fused_kernel<<<HH, TPB>>>(C, B, P, W, ld, (float*)d_out);
}